// round 1
// baseline (speedup 1.0000x reference)
#include <cuda_runtime.h>
#include <cuda_bf16.h>
#include <mma.h>

using namespace nvcuda;

// Problem constants
#define N_NODES 4096
#define F_IN    512
#define N_HEADS 4
#define N_HID   256
#define HD      (N_HEADS * N_HID)   // 1024
#define NPAD    1152                // 1024 + 4 (Z cols) padded to multiple of 128

// ---------------- scratch (device globals; no allocs allowed) ----------------
__device__ float          g_HT[N_NODES * HD];          // h@W  (fp32)
__device__ __nv_bfloat16  g_hh[N_NODES * F_IN];
__device__ __nv_bfloat16  g_hl[N_NODES * F_IN];
__device__ __nv_bfloat16  g_Wh[F_IN * HD];
__device__ __nv_bfloat16  g_Wl[F_IN * HD];
__device__ __nv_bfloat16  g_Abf[(size_t)N_NODES * N_NODES];
__device__ __nv_bfloat16  g_Vh[N_NODES * NPAD];
__device__ __nv_bfloat16  g_Vl[N_NODES * NPAD];
__device__ float          g_Y[N_NODES * NPAD];
__device__ float          g_tgt[N_HEADS * N_NODES];
__device__ float          g_tmax[N_HEADS];

// ---------------- elementwise kernels ----------------
__global__ void split_f32_kernel(const float* __restrict__ src,
                                 __nv_bfloat16* __restrict__ hi,
                                 __nv_bfloat16* __restrict__ lo, int n) {
    int i = blockIdx.x * blockDim.x + threadIdx.x;
    if (i < n) {
        float v = src[i];
        __nv_bfloat16 h = __float2bfloat16(v);
        hi[i] = h;
        lo[i] = __float2bfloat16(v - __bfloat162float(h));
    }
}

__global__ void adj_convert_kernel(const int* __restrict__ adj,
                                   __nv_bfloat16* __restrict__ out, int n) {
    int i = blockIdx.x * blockDim.x + threadIdx.x;
    if (i < n) out[i] = (adj[i] > 0) ? __float2bfloat16(1.0f) : __float2bfloat16(0.0f);
}

// tgt[h,m] = sum_d leaky_relu(HT[m, h*256+d]) * a[h*512 + 256 + d]
__global__ void tgt_kernel(const float* __restrict__ HT,
                           const float* __restrict__ a,
                           float* __restrict__ tgt) {
    int warp = (blockIdx.x * blockDim.x + threadIdx.x) >> 5;
    int lane = threadIdx.x & 31;
    if (warp >= N_HEADS * N_NODES) return;
    int h = warp >> 12;        // warp / 4096
    int m = warp & 4095;
    const float* row = HT + (size_t)m * HD + h * N_HID;
    const float* av  = a + h * (2 * N_HID) + N_HID;
    float s = 0.0f;
    #pragma unroll
    for (int d = lane; d < N_HID; d += 32) {
        float x = row[d];
        x = (x > 0.0f) ? x : 0.1f * x;
        s += x * av[d];
    }
    #pragma unroll
    for (int o = 16; o; o >>= 1) s += __shfl_xor_sync(0xFFFFFFFFu, s, o);
    if (lane == 0) tgt[h * N_NODES + m] = s;
}

__global__ void tmax_kernel(const float* __restrict__ tgt, float* __restrict__ tmax) {
    int h = blockIdx.x;
    __shared__ float sm[256];
    float m = -1e30f;
    for (int i = threadIdx.x; i < N_NODES; i += 256)
        m = fmaxf(m, tgt[h * N_NODES + i]);
    sm[threadIdx.x] = m;
    __syncthreads();
    for (int s = 128; s; s >>= 1) {
        if (threadIdx.x < s) sm[threadIdx.x] = fmaxf(sm[threadIdx.x], sm[threadIdx.x + s]);
        __syncthreads();
    }
    if (threadIdx.x == 0) tmax[h] = sm[0];
}

// V[n, h*256+d] = w[h,n]*HT[n,h*256+d];  V[n,1024+h] = w[h,n];  V[n,>=1028] = 0
__global__ void buildV_kernel(const float* __restrict__ HT,
                              const float* __restrict__ tgt,
                              const float* __restrict__ tmax,
                              __nv_bfloat16* __restrict__ Vh,
                              __nv_bfloat16* __restrict__ Vl) {
    int n = blockIdx.x;
    __shared__ float w[N_HEADS];
    if (threadIdx.x < N_HEADS)
        w[threadIdx.x] = expf(tgt[threadIdx.x * N_NODES + n] - tmax[threadIdx.x]);
    __syncthreads();
    for (int c = threadIdx.x; c < NPAD; c += 256) {
        float v;
        if (c < HD)            v = w[c >> 8] * HT[(size_t)n * HD + c];
        else if (c < HD + 4)   v = w[c - HD];
        else                   v = 0.0f;
        __nv_bfloat16 hi = __float2bfloat16(v);
        Vh[(size_t)n * NPAD + c] = hi;
        Vl[(size_t)n * NPAD + c] = __float2bfloat16(v - __bfloat162float(hi));
    }
}

// out[n,d] = 0.25 * sum_h Y[n, h*256+d] / Y[n, 1024+h]
__global__ void final_kernel(const float* __restrict__ Y, float* __restrict__ out) {
    int i = blockIdx.x * blockDim.x + threadIdx.x;
    if (i >= N_NODES * N_HID) return;
    int n = i >> 8, d = i & 255;
    const float* yr = Y + (size_t)n * NPAD;
    float acc = 0.0f;
    #pragma unroll
    for (int h = 0; h < N_HEADS; h++)
        acc += yr[h * N_HID + d] / yr[HD + h];
    out[i] = 0.25f * acc;
}

// ---------------- bf16 WMMA GEMM ----------------
// C[M,N] (fp32) = A1@B1 (+ A1@B2 if P12) (+ A2@B1 if P21); all inputs bf16 row-major.
// BM=128, BN=128, BK=32. 8 warps (2x4). Warp tile 64x32 => 4x2 fragments of 16x16.
#define BM 128
#define BN 128
#define BK 32
#define AKP 40    // BK + 8 pad
#define BNP 136   // BN + 8 pad

template <bool P12, bool P21>
__global__ __launch_bounds__(256)
void gemm_bf16(const __nv_bfloat16* __restrict__ A1,
               const __nv_bfloat16* __restrict__ A2,
               const __nv_bfloat16* __restrict__ B1,
               const __nv_bfloat16* __restrict__ B2,
               float* __restrict__ C, int M, int N, int K) {
    __shared__ __align__(16) __nv_bfloat16 sA1[BM][AKP];
    __shared__ __align__(16) __nv_bfloat16 sA2[BM][AKP];
    __shared__ __align__(16) __nv_bfloat16 sB1[BK][BNP];
    __shared__ __align__(16) __nv_bfloat16 sB2[BK][BNP];

    const int bm = blockIdx.y * BM;
    const int bn = blockIdx.x * BN;
    const int warpId = threadIdx.x >> 5;
    const int warpM = warpId >> 2;   // 0..1
    const int warpN = warpId & 3;    // 0..3

    wmma::fragment<wmma::accumulator, 16, 16, 16, float> acc[4][2];
    #pragma unroll
    for (int i = 0; i < 4; i++)
        #pragma unroll
        for (int j = 0; j < 2; j++) wmma::fill_fragment(acc[i][j], 0.0f);

    for (int k0 = 0; k0 < K; k0 += BK) {
        __syncthreads();
        // load A tiles: BM x BK, vectorized 8 bf16 per thread-op
        #pragma unroll
        for (int it = 0; it < 2; it++) {
            int idx = it * 256 + threadIdx.x;
            int r = idx >> 2;
            int c8 = (idx & 3) << 3;
            *(uint4*)&sA1[r][c8] = *(const uint4*)&A1[(size_t)(bm + r) * K + k0 + c8];
            if constexpr (P21)
                *(uint4*)&sA2[r][c8] = *(const uint4*)&A2[(size_t)(bm + r) * K + k0 + c8];
        }
        // load B tiles: BK x BN
        #pragma unroll
        for (int it = 0; it < 2; it++) {
            int idx = it * 256 + threadIdx.x;
            int r = idx >> 4;
            int c8 = (idx & 15) << 3;
            *(uint4*)&sB1[r][c8] = *(const uint4*)&B1[(size_t)(k0 + r) * N + bn + c8];
            if constexpr (P12)
                *(uint4*)&sB2[r][c8] = *(const uint4*)&B2[(size_t)(k0 + r) * N + bn + c8];
        }
        __syncthreads();

        #pragma unroll
        for (int kk = 0; kk < BK; kk += 16) {
            wmma::fragment<wmma::matrix_a, 16, 16, 16, __nv_bfloat16, wmma::row_major> a1f[4], a2f[4];
            wmma::fragment<wmma::matrix_b, 16, 16, 16, __nv_bfloat16, wmma::row_major> b1f[2], b2f[2];
            #pragma unroll
            for (int i = 0; i < 4; i++)
                wmma::load_matrix_sync(a1f[i], &sA1[warpM * 64 + i * 16][kk], AKP);
            if constexpr (P21) {
                #pragma unroll
                for (int i = 0; i < 4; i++)
                    wmma::load_matrix_sync(a2f[i], &sA2[warpM * 64 + i * 16][kk], AKP);
            }
            #pragma unroll
            for (int j = 0; j < 2; j++)
                wmma::load_matrix_sync(b1f[j], &sB1[kk][warpN * 32 + j * 16], BNP);
            if constexpr (P12) {
                #pragma unroll
                for (int j = 0; j < 2; j++)
                    wmma::load_matrix_sync(b2f[j], &sB2[kk][warpN * 32 + j * 16], BNP);
            }
            #pragma unroll
            for (int i = 0; i < 4; i++) {
                #pragma unroll
                for (int j = 0; j < 2; j++) {
                    wmma::mma_sync(acc[i][j], a1f[i], b1f[j], acc[i][j]);
                    if constexpr (P12) wmma::mma_sync(acc[i][j], a1f[i], b2f[j], acc[i][j]);
                    if constexpr (P21) wmma::mma_sync(acc[i][j], a2f[i], b1f[j], acc[i][j]);
                }
            }
        }
    }

    #pragma unroll
    for (int i = 0; i < 4; i++)
        #pragma unroll
        for (int j = 0; j < 2; j++)
            wmma::store_matrix_sync(&C[(size_t)(bm + warpM * 64 + i * 16) * N + bn + warpN * 32 + j * 16],
                                    acc[i][j], N, wmma::mem_row_major);
}

// ---------------- launch ----------------
extern "C" void kernel_launch(void* const* d_in, const int* in_sizes, int n_in,
                              void* d_out, int out_size) {
    // map inputs by element count (robust to ordering): h, adj, W, a
    const float* h = nullptr;
    const int*   adj = nullptr;
    const float* W = nullptr;
    const float* a = nullptr;
    for (int i = 0; i < n_in; i++) {
        switch (in_sizes[i]) {
            case N_NODES * F_IN:          h   = (const float*)d_in[i]; break;  // 2097152
            case N_NODES * N_NODES:       adj = (const int*)d_in[i];   break;  // 16777216
            case F_IN * HD:               W   = (const float*)d_in[i]; break;  // 524288
            case N_HEADS * 2 * N_HID:     a   = (const float*)d_in[i]; break;  // 2048
        }
    }
    float* out = (float*)d_out;

    float* HT; cudaGetSymbolAddress((void**)&HT, g_HT);
    __nv_bfloat16 *hh, *hl, *Wh, *Wl, *Abf, *Vh, *Vl;
    cudaGetSymbolAddress((void**)&hh, g_hh);
    cudaGetSymbolAddress((void**)&hl, g_hl);
    cudaGetSymbolAddress((void**)&Wh, g_Wh);
    cudaGetSymbolAddress((void**)&Wl, g_Wl);
    cudaGetSymbolAddress((void**)&Abf, g_Abf);
    cudaGetSymbolAddress((void**)&Vh, g_Vh);
    cudaGetSymbolAddress((void**)&Vl, g_Vl);
    float* Y;   cudaGetSymbolAddress((void**)&Y, g_Y);
    float* tgt; cudaGetSymbolAddress((void**)&tgt, g_tgt);
    float* tmx; cudaGetSymbolAddress((void**)&tmx, g_tmax);

    // 1. split h and W into bf16 hi/lo
    {
        int n = N_NODES * F_IN;
        split_f32_kernel<<<(n + 255) / 256, 256>>>(h, hh, hl, n);
    }
    {
        int n = F_IN * HD;
        split_f32_kernel<<<(n + 255) / 256, 256>>>(W, Wh, Wl, n);
    }
    // 2. adj -> bf16 {0,1}
    {
        int n = N_NODES * N_NODES;
        adj_convert_kernel<<<(n + 255) / 256, 256>>>(adj, Abf, n);
    }
    // 3. GEMM1: HT = h@W   (Ah*Bh + Ah*Bl + Al*Bh)
    gemm_bf16<true, true><<<dim3(HD / BN, N_NODES / BM), 256>>>(
        hh, hl, Wh, Wl, HT, N_NODES, HD, F_IN);
    // 4. tgt per (head, node)
    tgt_kernel<<<(N_HEADS * N_NODES) / 8, 256>>>(HT, a, tgt);
    // 5. per-head max
    tmax_kernel<<<N_HEADS, 256>>>(tgt, tmx);
    // 6. build weighted V (+ Z columns) hi/lo
    buildV_kernel<<<N_NODES, 256>>>(HT, tgt, tmx, Vh, Vl);
    // 7. GEMM2: Y = A@Vh + A@Vl
    gemm_bf16<true, false><<<dim3(NPAD / BN, N_NODES / BM), 256>>>(
        Abf, nullptr, Vh, Vl, Y, N_NODES, NPAD, N_NODES);
    // 8. divide + mean over heads
    {
        int n = N_NODES * N_HID;
        final_kernel<<<(n + 255) / 256, 256>>>(Y, out);
    }
    (void)out_size;
}

// round 3
// speedup vs baseline: 2.0963x; 2.0963x over previous
#include <cuda_runtime.h>
#include <cuda_bf16.h>
#include <cuda_fp16.h>
#include <cstdint>

// ---------------- problem constants ----------------
#define N_NODES 4096
#define F_IN    512
#define N_HEADS 4
#define N_HID   256
#define HD      1024     // N_HEADS*N_HID
#define NP2     1152     // 1024 feature cols + 4 Z cols, padded to 9*128

// ---------------- scratch (device globals; allocation-free) ----------------
__device__ uint16_t g_hh [N_NODES * F_IN];            // bf16 hi of h
__device__ uint16_t g_hl [N_NODES * F_IN];            // bf16 lo of h
__device__ uint16_t g_Wh [F_IN * HD];                 // bf16 hi of W
__device__ uint16_t g_Wl [F_IN * HD];                 // bf16 lo of W
__device__ uint16_t g_adjh[(size_t)N_NODES * N_NODES];// fp16 adjacency {0,1}
__device__ uint16_t g_V  [(size_t)N_NODES * NP2];     // fp16 weighted V
__device__ float    g_HT [N_NODES * HD];              // h@W fp32
__device__ float    g_Y  [(size_t)N_NODES * NP2];     // adj@V fp32
__device__ float    g_tgt [N_HEADS * N_NODES];
__device__ float    g_tmax[N_HEADS];

// ---------------- small helpers ----------------
__device__ __forceinline__ uint32_t smem_u32(const void* p) {
    uint32_t a;
    asm("{ .reg .u64 t; cvta.to.shared.u64 t, %1; cvt.u32.u64 %0, t; }" : "=r"(a) : "l"(p));
    return a;
}
__device__ __forceinline__ uint32_t pk(uint16_t a, uint16_t b) {
    return (uint32_t)a | ((uint32_t)b << 16);
}

__device__ __forceinline__ void cpasync16(uint32_t dst, const void* src) {
    asm volatile("cp.async.cg.shared.global [%0], [%1], 16;" :: "r"(dst), "l"(src));
}
__device__ __forceinline__ void cp_commit() {
    asm volatile("cp.async.commit_group;" ::: "memory");
}
template <int N>
__device__ __forceinline__ void cp_wait() {
    asm volatile("cp.async.wait_group %0;" :: "n"(N) : "memory");
}

__device__ __forceinline__ void ldsm4(uint32_t& r0, uint32_t& r1, uint32_t& r2, uint32_t& r3,
                                      uint32_t addr) {
    asm volatile("ldmatrix.sync.aligned.m8n8.x4.shared.b16 {%0,%1,%2,%3}, [%4];"
                 : "=r"(r0), "=r"(r1), "=r"(r2), "=r"(r3) : "r"(addr));
}
__device__ __forceinline__ void ldsm4t(uint32_t& r0, uint32_t& r1, uint32_t& r2, uint32_t& r3,
                                       uint32_t addr) {
    asm volatile("ldmatrix.sync.aligned.m8n8.x4.trans.shared.b16 {%0,%1,%2,%3}, [%4];"
                 : "=r"(r0), "=r"(r1), "=r"(r2), "=r"(r3) : "r"(addr));
}

template <bool BF>
__device__ __forceinline__ void mma16816(float* c, const uint32_t* a, const uint32_t* b) {
    if (BF)
        asm volatile(
            "mma.sync.aligned.m16n8k16.row.col.f32.bf16.bf16.f32 "
            "{%0,%1,%2,%3},{%4,%5,%6,%7},{%8,%9},{%0,%1,%2,%3};"
            : "+f"(c[0]), "+f"(c[1]), "+f"(c[2]), "+f"(c[3])
            : "r"(a[0]), "r"(a[1]), "r"(a[2]), "r"(a[3]), "r"(b[0]), "r"(b[1]));
    else
        asm volatile(
            "mma.sync.aligned.m16n8k16.row.col.f32.f16.f16.f32 "
            "{%0,%1,%2,%3},{%4,%5,%6,%7},{%8,%9},{%0,%1,%2,%3};"
            : "+f"(c[0]), "+f"(c[1]), "+f"(c[2]), "+f"(c[3])
            : "r"(a[0]), "r"(a[1]), "r"(a[2]), "r"(a[3]), "r"(b[0]), "r"(b[1]));
}

// ---------------- prep kernels ----------------
// fp32 -> bf16 hi/lo split, 8 elems per thread (grid sized exactly)
__global__ void split_kernel(const float4* __restrict__ src,
                             uint4* __restrict__ hh, uint4* __restrict__ hl) {
    int i = blockIdx.x * 256 + threadIdx.x;
    float4 v0 = src[2 * i], v1 = src[2 * i + 1];
    float f[8] = {v0.x, v0.y, v0.z, v0.w, v1.x, v1.y, v1.z, v1.w};
    uint16_t H[8], L[8];
    #pragma unroll
    for (int j = 0; j < 8; j++) {
        __nv_bfloat16 b = __float2bfloat16(f[j]);
        H[j] = __bfloat16_as_ushort(b);
        L[j] = __bfloat16_as_ushort(__float2bfloat16(f[j] - __bfloat162float(b)));
    }
    hh[i] = make_uint4(pk(H[0], H[1]), pk(H[2], H[3]), pk(H[4], H[5]), pk(H[6], H[7]));
    hl[i] = make_uint4(pk(L[0], L[1]), pk(L[2], L[3]), pk(L[4], L[5]), pk(L[6], L[7]));
}

// adjacency int32 -> fp16 {0,1}, 8 elems per thread
__global__ void prep_adj(const int4* __restrict__ adj, uint4* __restrict__ out) {
    int i = blockIdx.x * 256 + threadIdx.x;
    int4 a0 = adj[2 * i], a1 = adj[2 * i + 1];
    int v[8] = {a0.x, a0.y, a0.z, a0.w, a1.x, a1.y, a1.z, a1.w};
    uint16_t hv[8];
    #pragma unroll
    for (int j = 0; j < 8; j++) hv[j] = (v[j] > 0) ? (uint16_t)0x3C00 : (uint16_t)0;  // fp16 1.0
    out[i] = make_uint4(pk(hv[0], hv[1]), pk(hv[2], hv[3]), pk(hv[4], hv[5]), pk(hv[6], hv[7]));
}

// tgt[h,m] = sum_d leaky_relu(HT[m, h*256+d]) * a[h*512 + 256 + d]
__global__ void tgt_kernel(const float* __restrict__ HT, const float* __restrict__ a,
                           float* __restrict__ tgt) {
    int warp = (blockIdx.x * blockDim.x + threadIdx.x) >> 5;
    int lane = threadIdx.x & 31;
    if (warp >= N_HEADS * N_NODES) return;
    int h = warp >> 12, m = warp & 4095;
    const float* row = HT + (size_t)m * HD + h * N_HID;
    const float* av  = a + h * (2 * N_HID) + N_HID;
    float s = 0.0f;
    #pragma unroll
    for (int d = lane; d < N_HID; d += 32) {
        float x = row[d];
        x = (x > 0.0f) ? x : 0.1f * x;
        s += x * av[d];
    }
    #pragma unroll
    for (int o = 16; o; o >>= 1) s += __shfl_xor_sync(0xFFFFFFFFu, s, o);
    if (lane == 0) tgt[h * N_NODES + m] = s;
}

__global__ void tmax_kernel(const float* __restrict__ tgt, float* __restrict__ tmax) {
    int h = blockIdx.x;
    __shared__ float sm[256];
    float m = -1e30f;
    for (int i = threadIdx.x; i < N_NODES; i += 256)
        m = fmaxf(m, tgt[h * N_NODES + i]);
    sm[threadIdx.x] = m;
    __syncthreads();
    for (int s = 128; s; s >>= 1) {
        if (threadIdx.x < s) sm[threadIdx.x] = fmaxf(sm[threadIdx.x], sm[threadIdx.x + s]);
        __syncthreads();
    }
    if (threadIdx.x == 0) tmax[h] = sm[0];
}

// V[n, c<1024] = w'[h(c)] * HT[n,c];  V[n,1024+h] = w'[h];  V[n, >=1028] = 0
// w' = exp(tgt - tmax) * 4096  (scale cancels in the Y ratio, keeps fp16 in normal range)
__global__ void buildV(const float* __restrict__ HT, const float* __restrict__ tgt,
                       const float* __restrict__ tmax, __half* __restrict__ V) {
    int n = blockIdx.x;
    __shared__ float w[N_HEADS];
    if (threadIdx.x < N_HEADS)
        w[threadIdx.x] = expf(tgt[threadIdx.x * N_NODES + n] - tmax[threadIdx.x]) * 4096.0f;
    __syncthreads();
    __half* row = V + (size_t)n * NP2;
    const float* ht = HT + (size_t)n * HD;
    for (int c = threadIdx.x; c < NP2; c += 256) {
        float v;
        if (c < HD)          v = w[c >> 8] * ht[c];
        else if (c < HD + 4) v = w[c - HD];
        else                 v = 0.0f;
        row[c] = __float2half(v);
    }
}

// out[n,d] = 0.25 * sum_h Y[n, h*256+d] / Y[n, 1024+h]
__global__ void final_kernel(const float* __restrict__ Y, float* __restrict__ out) {
    int i = blockIdx.x * 256 + threadIdx.x;
    int n = i >> 8, d = i & 255;
    const float* yr = Y + (size_t)n * NP2;
    float acc = 0.0f;
    #pragma unroll
    for (int h = 0; h < N_HEADS; h++)
        acc += yr[h * N_HID + d] / yr[HD + h];
    out[i] = 0.25f * acc;
}

// ---------------- pipelined mma.sync GEMM ----------------
// C[M,N] (fp32) = A1@B1 (+ A1@B2 if NB==2) (+ A2@B1 if NA==2), 16-bit row-major inputs.
// BM=128 BN=128 BK=32; 8 warps (2x4), warp tile 64x32; cp.async multi-stage pipeline.
#define BM 128
#define BN 128
#define BK 32
#define A_STRIDE 80      // 64B data + 16B pad per A row (conflict-free ldmatrix)
#define B_STRIDE 272     // 256B data + 16B pad per B row
#define A_TILE   (BM * A_STRIDE)   // 10240 B
#define B_TILE   (BK * B_STRIDE)   // 8704 B

template <int NA, int NB, int STAGES, bool BF>
__global__ void __launch_bounds__(256)
gemm_mma(const uint16_t* __restrict__ A1, const uint16_t* __restrict__ A2,
         const uint16_t* __restrict__ B1, const uint16_t* __restrict__ B2,
         float* __restrict__ C, int N, int K) {
    extern __shared__ __align__(128) char smem[];
    const uint32_t sb = smem_u32(smem);
    const int tid = threadIdx.x, lane = tid & 31, wid = tid >> 5;
    const int wm = wid >> 2, wn = wid & 3;
    const int bm = blockIdx.y * BM, bn = blockIdx.x * BN;
    constexpr uint32_t STAGE = NA * A_TILE + NB * B_TILE;

    const uint16_t* Ap[2] = {A1, A2};
    const uint16_t* Bp[2] = {B1, B2};

    // cp.async index precompute: A 512 chunks of 16B (2/thread), B 512 chunks (2/thread)
    const int arow = tid >> 2, ac16 = tid & 3;
    const int brow = tid >> 4, bc16 = tid & 15;

    auto load_stage = [&](int slot, int k0) {
        uint32_t base = sb + slot * STAGE;
        #pragma unroll
        for (int p = 0; p < NA; p++) {
            uint32_t ab = base + p * A_TILE;
            const uint16_t* g = Ap[p] + (size_t)(bm + arow) * K + k0 + ac16 * 8;
            cpasync16(ab + arow * A_STRIDE + ac16 * 16, g);
            cpasync16(ab + (arow + 64) * A_STRIDE + ac16 * 16, g + (size_t)64 * K);
        }
        #pragma unroll
        for (int p = 0; p < NB; p++) {
            uint32_t bb = base + NA * A_TILE + p * B_TILE;
            const uint16_t* g = Bp[p] + (size_t)(k0 + brow) * N + bn + bc16 * 8;
            cpasync16(bb + brow * B_STRIDE + bc16 * 16, g);
            cpasync16(bb + (brow + 16) * B_STRIDE + bc16 * 16, g + (size_t)16 * N);
        }
        cp_commit();
    };

    const int iters = K / BK;
    #pragma unroll
    for (int s = 0; s < STAGES - 1; s++)
        load_stage(s, s * BK);

    float acc[4][4][4];
    #pragma unroll
    for (int i = 0; i < 4; i++)
        #pragma unroll
        for (int j = 0; j < 4; j++)
            #pragma unroll
            for (int r = 0; r < 4; r++) acc[i][j][r] = 0.0f;

    // ldmatrix per-lane addressing (same pattern for A and trans-B)
    const int lrow = lane & 15;          // row within 16-row block
    const int lcol = lane >> 4;          // 0/1 -> +8 cols (16B)

    for (int it = 0; it < iters; ++it) {
        cp_wait<STAGES - 2>();
        __syncthreads();
        if (it + STAGES - 1 < iters)
            load_stage((it + STAGES - 1) % STAGES, (it + STAGES - 1) * BK);

        uint32_t base = sb + (it % STAGES) * STAGE;
        #pragma unroll
        for (int ks = 0; ks < 2; ks++) {
            uint32_t af[2][4][4];
            uint32_t bf[2][2][4];
            #pragma unroll
            for (int p = 0; p < NA; p++)
                #pragma unroll
                for (int mt = 0; mt < 4; mt++) {
                    uint32_t addr = base + p * A_TILE
                                  + (wm * 64 + mt * 16 + lrow) * A_STRIDE
                                  + ks * 32 + lcol * 16;
                    ldsm4(af[p][mt][0], af[p][mt][1], af[p][mt][2], af[p][mt][3], addr);
                }
            #pragma unroll
            for (int p = 0; p < NB; p++)
                #pragma unroll
                for (int nt2 = 0; nt2 < 2; nt2++) {
                    uint32_t addr = base + NA * A_TILE + p * B_TILE
                                  + (ks * 16 + lrow) * B_STRIDE
                                  + (wn * 32 + nt2 * 16 + lcol * 8) * 2;
                    ldsm4t(bf[p][nt2][0], bf[p][nt2][1], bf[p][nt2][2], bf[p][nt2][3], addr);
                }
            #pragma unroll
            for (int mt = 0; mt < 4; mt++)
                #pragma unroll
                for (int nt = 0; nt < 4; nt++) {
                    const uint32_t* b0 = &bf[0][nt >> 1][(nt & 1) * 2];
                    mma16816<BF>(acc[mt][nt], af[0][mt], b0);
                    if (NB == 2) mma16816<BF>(acc[mt][nt], af[0][mt], &bf[1][nt >> 1][(nt & 1) * 2]);
                    if (NA == 2) mma16816<BF>(acc[mt][nt], af[1][mt], b0);
                }
        }
    }

    // epilogue: fp32 direct stores
    const int row0 = bm + wm * 64;
    const int col0 = bn + wn * 32;
    #pragma unroll
    for (int mt = 0; mt < 4; mt++)
        #pragma unroll
        for (int nt = 0; nt < 4; nt++) {
            int r = row0 + mt * 16 + (lane >> 2);
            int c = col0 + nt * 8 + (lane & 3) * 2;
            *(float2*)&C[(size_t)r * N + c]       = make_float2(acc[mt][nt][0], acc[mt][nt][1]);
            *(float2*)&C[(size_t)(r + 8) * N + c] = make_float2(acc[mt][nt][2], acc[mt][nt][3]);
        }
}

// ---------------- launch ----------------
extern "C" void kernel_launch(void* const* d_in, const int* in_sizes, int n_in,
                              void* d_out, int out_size) {
    const float* h = nullptr; const int* adj = nullptr;
    const float* W = nullptr; const float* a = nullptr;
    for (int i = 0; i < n_in; i++) {
        switch (in_sizes[i]) {
            case N_NODES * F_IN:      h   = (const float*)d_in[i]; break;
            case N_NODES * N_NODES:   adj = (const int*)d_in[i];   break;
            case F_IN * HD:           W   = (const float*)d_in[i]; break;
            case N_HEADS * 2 * N_HID: a   = (const float*)d_in[i]; break;
        }
    }
    float* out = (float*)d_out;

    uint16_t *hh, *hl, *Wh, *Wl, *adjh, *V;
    float *HT, *Y, *tgt, *tmx;
    cudaGetSymbolAddress((void**)&hh,  g_hh);
    cudaGetSymbolAddress((void**)&hl,  g_hl);
    cudaGetSymbolAddress((void**)&Wh,  g_Wh);
    cudaGetSymbolAddress((void**)&Wl,  g_Wl);
    cudaGetSymbolAddress((void**)&adjh, g_adjh);
    cudaGetSymbolAddress((void**)&V,   g_V);
    cudaGetSymbolAddress((void**)&HT,  g_HT);
    cudaGetSymbolAddress((void**)&Y,   g_Y);
    cudaGetSymbolAddress((void**)&tgt, g_tgt);
    cudaGetSymbolAddress((void**)&tmx, g_tmax);

    const int smem1 = 3 * (2 * A_TILE + 2 * B_TILE);   // 113664 (GEMM1: NA=2,NB=2,S=3)
    const int smem2 = 4 * (1 * A_TILE + 1 * B_TILE);   //  75776 (GEMM2: NA=1,NB=1,S=4)
    cudaFuncSetAttribute(gemm_mma<2, 2, 3, true>,
                         cudaFuncAttributeMaxDynamicSharedMemorySize, smem1);
    cudaFuncSetAttribute(gemm_mma<1, 1, 4, false>,
                         cudaFuncAttributeMaxDynamicSharedMemorySize, smem2);

    // 1. operand prep (all row-major elementwise)
    split_kernel<<<1024, 256>>>((const float4*)h, (uint4*)hh, (uint4*)hl);   // 2M elems
    split_kernel<<<256, 256>>>((const float4*)W, (uint4*)Wh, (uint4*)Wl);    // 512K elems
    prep_adj<<<8192, 256>>>((const int4*)adj, (uint4*)adjh);                 // 16M elems

    // 2. GEMM1: HT = h@W (dual-bf16, 3 products)  M=4096 N=1024 K=512
    gemm_mma<2, 2, 3, true><<<dim3(HD / BN, N_NODES / BM), 256, smem1>>>(
        hh, hl, Wh, Wl, HT, HD, F_IN);

    // 3. attention scalars + weighted V
    tgt_kernel <<<2048, 256>>>(HT, a, tgt);
    tmax_kernel<<<N_HEADS, 256>>>(tgt, tmx);
    buildV     <<<N_NODES, 256>>>(HT, tgt, tmx, (__half*)V);

    // 4. GEMM2: Y = adj@V (single fp16)  M=4096 N=1152 K=4096
    gemm_mma<1, 1, 4, false><<<dim3(NP2 / BN, N_NODES / BM), 256, smem2>>>(
        adjh, nullptr, V, nullptr, Y, NP2, N_NODES);

    // 5. normalize + head mean
    final_kernel<<<N_NODES, 256>>>(Y, out);
    (void)out_size;
}